// round 15
// baseline (speedup 1.0000x reference)
#include <cuda_runtime.h>
#include <cuda_fp16.h>
#include <math.h>
#include <stdint.h>

#define NB   64
#define NPER 256
#define DIN  256
#define DOUT 128
#define EPER 8192
#define ADJ_N 8192
#define ADJ_ELEMS (67108864u)
#define NROWS (NB*NPER)          // 16384

// ---------------- scratch ----------------
__device__ float g_T[NROWS*512];          // only cols 0..127 (f_top) and 256..383 (p_top) used
__device__ float g_A[NB*NPER*NPER];       // dense adjacency counts (fp32)
__device__ float g_AG[NB*NPER*256];       // A @ [T_fbot|T_pbot]
__device__ float g_ideg[NROWS];
// fp16x2 fragment arrays (uint32 words)
__device__ unsigned int g_Xf[NROWS*128];      // X      A-frag [mt][kc][lane][4]
__device__ unsigned int g_WTf[64*1024];       // Wcat^T B-frag [nt64][kc][lane][2]
__device__ unsigned int g_Afrag[NB*16*2048];  // A (exact) A-frag [b][mt][kc][lane][4]
__device__ unsigned int g_Tf[NB*32768];       // T_bot  B-frag [b][nt32][kc][lane][2]
__device__ unsigned int g_Sf[NB*16384];       // assign B-frag [b][nt16][kc][lane][2]
__device__ unsigned int g_Ff[NB*16384];       // feat   B-frag
__device__ unsigned int g_ASf[NB*16384];      // AS     B-frag
__device__ unsigned int g_STf[NB*16384];      // S^T    A-frag [b][mt8][kc][lane][4]

// ---------------- mma.sync fp16 ----------
__device__ __forceinline__ void mma16816(float* c, const uint32_t* a, const uint32_t* b) {
    asm volatile(
        "mma.sync.aligned.m16n8k16.row.col.f32.f16.f16.f32 "
        "{%0,%1,%2,%3}, {%4,%5,%6,%7}, {%8,%9}, {%0,%1,%2,%3};"
        : "+f"(c[0]), "+f"(c[1]), "+f"(c[2]), "+f"(c[3])
        : "r"(a[0]), "r"(a[1]), "r"(a[2]), "r"(a[3]), "r"(b[0]), "r"(b[1]));
}

__device__ __forceinline__ unsigned int pack_h2(float a, float b) {
    __half2 p = __floats2half2_rn(a, b);
    return *reinterpret_cast<unsigned int*>(&p);
}

// ---------------- K-buildA: dense adjacency + degrees + A fragments -----------
// one block per graph; block owns everything for its graph.
__global__ void __launch_bounds__(256) k_buildA(const int* __restrict__ esrc,
                                                const int* __restrict__ edst) {
    int b = blockIdx.x, t = threadIdx.x;
    float* A = g_A + (size_t)b*65536;
    float4* A4 = (float4*)A;
    for (int i = t; i < 16384; i += 256) A4[i] = make_float4(0.f, 0.f, 0.f, 0.f);
    __shared__ int scnt[NPER];
    if (t < 256) scnt[t] = 0;
    __syncthreads();
    const int* s = esrc + b*EPER;
    const int* d = edst + b*EPER;
    for (int e = t; e < EPER; e += 256) {
        int dst = d[e], src = s[e];
        atomicAdd(&scnt[dst], 1);
        atomicAdd(&A[dst*256 + src], 1.0f);
    }
    __syncthreads();
    if (t < 256) {
        int c = scnt[t];
        g_ideg[b*NPER + t] = 1.0f / (float)(c > 0 ? c : 1);
    }
    __syncthreads();
    // convert this graph's A to exact fp16 A-fragments (L2-hot reads)
    #pragma unroll 4
    for (int k = 0; k < 128; k++) {
        int idx = t + k*256;                // [0, 32768)
        int mt = idx >> 11, w = idx & 2047;
        int reg = w & 3, lane = (w >> 2) & 31, kc = w >> 7;
        int g = lane >> 2, tg = lane & 3;
        int row = mt*16 + g + (reg & 1)*8;
        int col = kc*16 + tg*2 + (reg >> 1)*8;
        g_Afrag[(size_t)(b*16 + mt)*2048 + w] = pack_h2(A[row*256 + col], A[row*256 + col + 1]);
    }
}

// ---------------- K-prep: X A-frags; W B-frags (single fp16) --------
__global__ void __launch_bounds__(256) k_prep(
        const float* __restrict__ h,
        const float* __restrict__ Wf, const float* __restrict__ Wp) {
    __shared__ float hs[16*256];
    int t = threadIdx.x;
    if (blockIdx.x < 1024) {
        int mt = blockIdx.x;
        const float4* src = (const float4*)(h + (size_t)mt*16*DIN);
        #pragma unroll
        for (int k = 0; k < 4; k++)
            ((float4*)hs)[t + k*256] = src[t + k*256];
        __syncthreads();
        #pragma unroll
        for (int k = 0; k < 8; k++) {
            int w = t + k*256;
            int reg = w & 3, lane = (w >> 2) & 31, kc = w >> 7;
            int g = lane >> 2, tg = lane & 3;
            int row = g + (reg & 1)*8;
            int wc = tg + (reg >> 1)*4;
            const float* hp = hs + row*256 + (kc*8 + wc)*2;
            g_Xf[(size_t)mt*2048 + w] = pack_h2(hp[0], hp[1]);
        }
    } else {
        int widx = (blockIdx.x - 1024)*256 + t;   // [0, 65536)
        int reg = widx & 1, lane = (widx >> 1) & 31, kc = (widx >> 6) & 15, nt = widx >> 10;
        int g = lane >> 2, tg = lane & 3;
        int n = nt*8 + g;
        int w = tg + reg*4;
        int k = (kc*8 + w)*2;
        int seg = n >> 7;
        const float* Wb = (seg < 2) ? Wf : Wp;
        int col = n & 127;
        int krow = k + ((seg & 1) ? 256 : 0);
        float x0 = Wb[(size_t)krow*128 + col];
        float x1 = Wb[(size_t)(krow+1)*128 + col];
        g_WTf[widx] = pack_h2(x0, x1);
    }
}

// ---------------- K-gemm: T = X @ Wcat (1-pass fp16) ----------------
// grid (128, 4); y in {0,2}: write fp32 T (top halves); y in {1,3}: emit Tf frags.
__global__ void __launch_bounds__(256) k_gemm_mma() {
    extern __shared__ float smT[];      // 128 x 128 staging (64KB) for frag emission
    int t = threadIdx.x, lane = t & 31, w = t >> 5;
    int wm = w & 1, wn = w >> 1;
    int mt0 = blockIdx.x*8 + wm*4;
    int nt0 = blockIdx.y*16 + wn*4;

    float acc[4][4][4];
    #pragma unroll
    for (int i = 0; i < 4; i++)
        #pragma unroll
        for (int j = 0; j < 4; j++)
            #pragma unroll
            for (int r = 0; r < 4; r++) acc[i][j][r] = 0.f;

    const uint4* X4 = (const uint4*)g_Xf;
    const uint2* W2 = (const uint2*)g_WTf;

    for (int kc = 0; kc < 16; kc++) {
        uint4 Af[4];
        uint2 Bf[4];
        #pragma unroll
        for (int i = 0; i < 4; i++)
            Af[i] = X4[((mt0 + i)*16 + kc)*32 + lane];
        #pragma unroll
        for (int j = 0; j < 4; j++)
            Bf[j] = W2[((nt0 + j)*16 + kc)*32 + lane];
        #pragma unroll
        for (int i = 0; i < 4; i++)
            #pragma unroll
            for (int j = 0; j < 4; j++)
                mma16816(acc[i][j], (const uint32_t*)&Af[i], (const uint32_t*)&Bf[j]);
    }

    int g = lane >> 2, tg = lane & 3;
    if ((blockIdx.y & 1) == 0) {
        #pragma unroll
        for (int i = 0; i < 4; i++) {
            #pragma unroll
            for (int j = 0; j < 4; j++) {
                size_t row = (size_t)(mt0 + i)*16 + g;
                size_t col = (size_t)(nt0 + j)*8 + tg*2;
                *(float2*)(g_T + row*512 + col)       = make_float2(acc[i][j][0], acc[i][j][1]);
                *(float2*)(g_T + (row + 8)*512 + col) = make_float2(acc[i][j][2], acc[i][j][3]);
            }
        }
    } else {
        #pragma unroll
        for (int i = 0; i < 4; i++) {
            #pragma unroll
            for (int j = 0; j < 4; j++) {
                int row = (wm*4 + i)*16 + g;
                int col = (wn*4 + j)*8 + tg*2;
                *(float2*)(smT + row*128 + col)       = make_float2(acc[i][j][0], acc[i][j][1]);
                *(float2*)(smT + (row + 8)*128 + col) = make_float2(acc[i][j][2], acc[i][j][3]);
            }
        }
        __syncthreads();
        int b = blockIdx.x >> 1, half = blockIdx.x & 1;
        int ntbase = (blockIdx.y == 1) ? 0 : 16;
        #pragma unroll
        for (int k = 0; k < 32; k++) {
            int w2 = t + k*256;               // [0, 8192)
            int reg = w2 & 1, ln = (w2 >> 1) & 31, ntl = (w2 >> 6) & 15, kcl = w2 >> 10;
            int gg = ln >> 2, tt = ln & 3;
            int n = ntl*8 + gg;
            int k0 = tt*2 + reg*8;
            int row = kcl*16 + k0;
            g_Tf[(size_t)b*32768 + (ntbase + ntl)*1024 + (half*8 + kcl)*64 + ln*2 + reg] =
                pack_h2(smT[row*128 + n], smT[(row + 1)*128 + n]);
        }
    }
}

// ---------------- K-agg2: AG = A @ [T_fbot|T_pbot] (1-pass) --------------------
__global__ void __launch_bounds__(256) k_agg2() {
    int t = threadIdx.x, lane = t & 31, w = t >> 5;
    int b = blockIdx.x, mh = blockIdx.y, nh = blockIdx.z;
    int wm = w & 1, wn = w >> 1;
    int mt0 = mh*8 + wm*4;
    int nt0 = nh*16 + wn*4;

    float acc[4][4][4];
    #pragma unroll
    for (int i = 0; i < 4; i++)
        #pragma unroll
        for (int j = 0; j < 4; j++)
            #pragma unroll
            for (int r = 0; r < 4; r++) acc[i][j][r] = 0.f;

    const uint4* A4 = (const uint4*)g_Afrag;
    const uint2* B2 = (const uint2*)g_Tf;

    for (int kc = 0; kc < 16; kc++) {
        uint4 Af[4];
        uint2 Bf[4];
        #pragma unroll
        for (int i = 0; i < 4; i++)
            Af[i] = A4[(size_t)(b*16 + mt0 + i)*512 + kc*32 + lane];
        #pragma unroll
        for (int j = 0; j < 4; j++)
            Bf[j] = B2[(size_t)b*16384 + (nt0 + j)*512 + kc*32 + lane];
        #pragma unroll
        for (int i = 0; i < 4; i++)
            #pragma unroll
            for (int j = 0; j < 4; j++)
                mma16816(acc[i][j], (const uint32_t*)&Af[i], (const uint32_t*)&Bf[j]);
    }

    int g = lane >> 2, tg = lane & 3;
    #pragma unroll
    for (int i = 0; i < 4; i++) {
        #pragma unroll
        for (int j = 0; j < 4; j++) {
            size_t row = (size_t)(mt0 + i)*16 + g;
            size_t col = (size_t)(nt0 + j)*8 + tg*2;
            *(float2*)(g_AG + ((size_t)b*256 + row)*256 + col)     = make_float2(acc[i][j][0], acc[i][j][1]);
            *(float2*)(g_AG + ((size_t)b*256 + row + 8)*256 + col) = make_float2(acc[i][j][2], acc[i][j][3]);
        }
    }
}

// ---------------- K-epi: z -> norm/relu(/softmax); emit S,F,S^T fragments ------
__global__ void __launch_bounds__(256) k_epi(const float* __restrict__ bf,
                                             const float* __restrict__ bp) {
    __shared__ float smF[16*128];
    __shared__ float smS[16*128];
    int b = blockIdx.x >> 4, kc = blockIdx.x & 15;
    int t = threadIdx.x, w = t >> 5, l = t & 31;

    #pragma unroll
    for (int i = 0; i < 4; i++) {
        int task = w*4 + i;
        int which = task >> 4, nl = task & 15;
        int gi = b*256 + kc*16 + nl;
        const float* bias = which ? bp : bf;
        float4 bias4 = *(const float4*)(bias + l*4);
        float4 top = *(const float4*)(g_T + (size_t)gi*512 + which*256 + l*4);
        float4 ag  = *(const float4*)(g_AG + (size_t)gi*256 + which*128 + l*4);
        float ideg = g_ideg[gi];

        float z0 = fmaf(ideg, ag.x, top.x) + bias4.x;
        float z1 = fmaf(ideg, ag.y, top.y) + bias4.y;
        float z2 = fmaf(ideg, ag.z, top.z) + bias4.z;
        float z3 = fmaf(ideg, ag.w, top.w) + bias4.w;

        float ss = z0*z0 + z1*z1 + z2*z2 + z3*z3;
        #pragma unroll
        for (int o = 16; o > 0; o >>= 1) ss += __shfl_xor_sync(0xffffffffu, ss, o);
        float inv = rsqrtf(fmaxf(ss, 1e-24f));
        z0 = fmaxf(z0*inv, 0.f); z1 = fmaxf(z1*inv, 0.f);
        z2 = fmaxf(z2*inv, 0.f); z3 = fmaxf(z3*inv, 0.f);

        if (which == 0) {
            smF[nl*128 + l*4 + 0] = z0;
            smF[nl*128 + l*4 + 1] = z1;
            smF[nl*128 + l*4 + 2] = z2;
            smF[nl*128 + l*4 + 3] = z3;
        } else {
            float m = fmaxf(fmaxf(z0, z1), fmaxf(z2, z3));
            #pragma unroll
            for (int o = 16; o > 0; o >>= 1) m = fmaxf(m, __shfl_xor_sync(0xffffffffu, m, o));
            float e0 = __expf(z0 - m), e1 = __expf(z1 - m);
            float e2 = __expf(z2 - m), e3 = __expf(z3 - m);
            float s = (e0 + e1) + (e2 + e3);
            #pragma unroll
            for (int o = 16; o > 0; o >>= 1) s += __shfl_xor_sync(0xffffffffu, s, o);
            float isum = 1.0f / s;
            smS[nl*128 + l*4 + 0] = e0*isum;
            smS[nl*128 + l*4 + 1] = e1*isum;
            smS[nl*128 + l*4 + 2] = e2*isum;
            smS[nl*128 + l*4 + 3] = e3*isum;
        }
    }
    __syncthreads();

    #pragma unroll
    for (int k = 0; k < 4; k++) {
        int w2 = t + k*256;
        int reg = w2 & 1, lane = (w2 >> 1) & 31, nt = w2 >> 6;
        int g = lane >> 2, tg = lane & 3;
        int n = nt*8 + g;
        int k0 = tg*2 + reg*8;
        size_t idx = (size_t)b*16384 + nt*1024 + kc*64 + (w2 & 63);
        g_Sf[idx] = pack_h2(smS[k0*128 + n], smS[(k0+1)*128 + n]);
        g_Ff[idx] = pack_h2(smF[k0*128 + n], smF[(k0+1)*128 + n]);
    }
    #pragma unroll
    for (int k = 0; k < 4; k++) {
        int w2 = t + k*256;
        int reg = w2 & 3, lane = (w2 >> 2) & 31, mt = w2 >> 7;
        int g = lane >> 2, tg = lane & 3;
        int m = mt*16 + g + (reg & 1)*8;
        int k0 = tg*2 + (reg >> 1)*8;
        g_STf[(size_t)b*16384 + mt*2048 + kc*128 + lane*4 + reg] =
            pack_h2(smS[k0*128 + m], smS[(k0+1)*128 + m]);
    }
}

// ---------------- K-as2: AS = A @ S -> emit ASf frags directly --------
__global__ void __launch_bounds__(256) k_as2() {
    extern __shared__ float smT[];      // 128 x 128
    int t = threadIdx.x, lane = t & 31, w = t >> 5;
    int b = blockIdx.x, mh = blockIdx.y;
    int wm = w & 1, wn = w >> 1;
    int mt0 = mh*8 + wm*4;
    int nt0 = wn*4;

    float acc[4][4][4];
    #pragma unroll
    for (int i = 0; i < 4; i++)
        #pragma unroll
        for (int j = 0; j < 4; j++)
            #pragma unroll
            for (int r = 0; r < 4; r++) acc[i][j][r] = 0.f;

    const uint4* A4 = (const uint4*)g_Afrag;
    const uint2* B2 = (const uint2*)g_Sf;

    for (int kc = 0; kc < 16; kc++) {
        uint4 Af[4];
        uint2 Bf[4];
        #pragma unroll
        for (int i = 0; i < 4; i++)
            Af[i] = A4[(size_t)(b*16 + mt0 + i)*512 + kc*32 + lane];
        #pragma unroll
        for (int j = 0; j < 4; j++)
            Bf[j] = B2[(size_t)b*8192 + (nt0 + j)*512 + kc*32 + lane];
        #pragma unroll
        for (int i = 0; i < 4; i++)
            #pragma unroll
            for (int j = 0; j < 4; j++)
                mma16816(acc[i][j], (const uint32_t*)&Af[i], (const uint32_t*)&Bf[j]);
    }

    int g = lane >> 2, tg = lane & 3;
    #pragma unroll
    for (int i = 0; i < 4; i++) {
        #pragma unroll
        for (int j = 0; j < 4; j++) {
            int row = (wm*4 + i)*16 + g;
            int col = (wn*4 + j)*8 + tg*2;
            *(float2*)(smT + row*128 + col)       = make_float2(acc[i][j][0], acc[i][j][1]);
            *(float2*)(smT + (row + 8)*128 + col) = make_float2(acc[i][j][2], acc[i][j][3]);
        }
    }
    __syncthreads();
    #pragma unroll
    for (int k = 0; k < 32; k++) {
        int w2 = t + k*256;               // [0, 8192)
        int reg = w2 & 1, ln = (w2 >> 1) & 31, ntl = (w2 >> 6) & 15, kcl = w2 >> 10;
        int gg = ln >> 2, tt = ln & 3;
        int n = ntl*8 + gg;
        int k0 = tt*2 + reg*8;
        int row = kcl*16 + k0;
        g_ASf[(size_t)b*16384 + ntl*1024 + (mh*8 + kcl)*64 + ln*2 + reg] =
            pack_h2(smT[row*128 + n], smT[(row + 1)*128 + n]);
    }
}

// ---------------- K-pool: D = S^T @ (F or AS) via HMMA ----------
// which passed as param so the two halves can be scheduled independently.
__global__ void __launch_bounds__(256) k_pool_mma(float* __restrict__ out, int which) {
    int t = threadIdx.x, lane = t & 31, w = t >> 5;
    int b = blockIdx.x;
    int wm = w & 1, wn = w >> 1;
    int mt0 = wm*4;
    int nt0 = wn*4;

    float acc[4][4][4];
    #pragma unroll
    for (int i = 0; i < 4; i++)
        #pragma unroll
        for (int j = 0; j < 4; j++)
            #pragma unroll
            for (int r = 0; r < 4; r++) acc[i][j][r] = 0.f;

    const uint4* A4 = (const uint4*)g_STf;
    const uint2* B2 = (const uint2*)(which ? g_ASf : g_Ff);

    for (int kc = 0; kc < 16; kc++) {
        uint4 Af[4];
        uint2 Bf[4];
        #pragma unroll
        for (int i = 0; i < 4; i++)
            Af[i] = A4[(size_t)b*4096 + (mt0 + i)*512 + kc*32 + lane];
        #pragma unroll
        for (int j = 0; j < 4; j++)
            Bf[j] = B2[(size_t)b*8192 + (nt0 + j)*512 + kc*32 + lane];
        #pragma unroll
        for (int i = 0; i < 4; i++)
            #pragma unroll
            for (int j = 0; j < 4; j++)
                mma16816(acc[i][j], (const uint32_t*)&Af[i], (const uint32_t*)&Bf[j]);
    }

    int g = lane >> 2, tg = lane & 3;
    #pragma unroll
    for (int i = 0; i < 4; i++) {
        #pragma unroll
        for (int j = 0; j < 4; j++) {
            size_t row = (size_t)(mt0 + i)*16 + g;
            size_t col = (size_t)(nt0 + j)*8 + tg*2;
            size_t grow = (size_t)b*128 + row;
            size_t base = which ? (grow*ADJ_N + (size_t)b*128 + col)
                                : ((size_t)ADJ_ELEMS + grow*DOUT + col);
            *(float2*)(out + base) = make_float2(acc[i][j][0], acc[i][j][1]);
            size_t grow2 = grow + 8;
            size_t base2 = which ? (grow2*ADJ_N + (size_t)b*128 + col)
                                 : ((size_t)ADJ_ELEMS + grow2*DOUT + col);
            *(float2*)(out + base2) = make_float2(acc[i][j][2], acc[i][j][3]);
        }
    }
}

// ---------------- launch ----------------
extern "C" void kernel_launch(void* const* d_in, const int* in_sizes, int n_in,
                              void* d_out, int out_size) {
    const float* h    = (const float*)d_in[0];
    const int*   esrc = (const int*)d_in[1];
    const int*   edst = (const int*)d_in[2];
    const float* Wf   = (const float*)d_in[3];
    const float* bf   = (const float*)d_in[4];
    const float* Wp   = (const float*)d_in[5];
    const float* bp   = (const float*)d_in[6];
    float* out = (float*)d_out;

    static cudaStream_t s_ms = nullptr, s_bd = nullptr;
    static cudaEvent_t  e_fork = nullptr, e_build = nullptr, e_ms = nullptr;
    static bool attr_done = false;
    if (!s_ms) {
        cudaStreamCreateWithFlags(&s_ms, cudaStreamNonBlocking);
        cudaStreamCreateWithFlags(&s_bd, cudaStreamNonBlocking);
        cudaEventCreateWithFlags(&e_fork,  cudaEventDisableTiming);
        cudaEventCreateWithFlags(&e_build, cudaEventDisableTiming);
        cudaEventCreateWithFlags(&e_ms,    cudaEventDisableTiming);
    }
    if (!attr_done) {
        cudaFuncSetAttribute(k_gemm_mma, cudaFuncAttributeMaxDynamicSharedMemorySize, 65536);
        cudaFuncSetAttribute(k_as2,      cudaFuncAttributeMaxDynamicSharedMemorySize, 65536);
        attr_done = true;
    }

    // fork: memset and buildA both start at t=0 on independent streams
    cudaEventRecord(e_fork, 0);
    cudaStreamWaitEvent(s_ms, e_fork, 0);
    cudaMemsetAsync(d_out, 0, (size_t)ADJ_ELEMS * sizeof(float), s_ms);
    cudaEventRecord(e_ms, s_ms);
    cudaStreamWaitEvent(s_bd, e_fork, 0);
    k_buildA<<<NB, 256, 0, s_bd>>>(esrc, edst);
    cudaEventRecord(e_build, s_bd);

    // main stream
    k_prep<<<1280, 256>>>(h, Wf, Wp);
    k_gemm_mma<<<dim3(128, 4), 256, 65536>>>();
    cudaStreamWaitEvent(0, e_build, 0);
    k_agg2<<<dim3(NB, 2, 2), 256>>>();
    k_epi<<<1024, 256>>>(bf, bp);
    k_pool_mma<<<NB, 256>>>(out, 0);     // h_pool region: no memset dependency
    k_as2<<<dim3(NB, 2), 256, 65536>>>();
    cudaStreamWaitEvent(0, e_ms, 0);
    k_pool_mma<<<NB, 256>>>(out, 1);     // adj diagonal blocks: after memset
}

// round 16
// speedup vs baseline: 1.2530x; 1.2530x over previous
#include <cuda_runtime.h>
#include <cuda_fp16.h>
#include <math.h>
#include <stdint.h>

#define NB   64
#define NPER 256
#define DIN  256
#define DOUT 128
#define EPER 8192
#define ADJ_N 8192
#define ADJ_ELEMS (67108864u)
#define NROWS (NB*NPER)          // 16384

// ---------------- scratch ----------------
__device__ float g_T[NROWS*512];          // only cols 0..127 (f_top) and 256..383 (p_top) used
__device__ float g_A[NB*NPER*NPER];       // dense adjacency counts (fp32)
__device__ float g_AG[NB*NPER*256];       // A @ [T_fbot|T_pbot]
__device__ float g_ideg[NROWS];
// fp16x2 fragment arrays (uint32 words)
__device__ unsigned int g_Xf[NROWS*128];      // X      A-frag [mt][kc][lane][4]
__device__ unsigned int g_WTf[64*1024];       // Wcat^T B-frag [nt64][kc][lane][2]
__device__ unsigned int g_Afrag[NB*16*2048];  // A (exact) A-frag [b][mt][kc][lane][4]
__device__ unsigned int g_Tf[NB*32768];       // T_bot  B-frag [b][nt32][kc][lane][2]
__device__ unsigned int g_Sf[NB*16384];       // assign B-frag [b][nt16][kc][lane][2]
__device__ unsigned int g_Ff[NB*16384];       // feat   B-frag
__device__ unsigned int g_ASf[NB*16384];      // AS     B-frag
__device__ unsigned int g_STf[NB*16384];      // S^T    A-frag [b][mt8][kc][lane][4]

// ---------------- mma.sync fp16 ----------
__device__ __forceinline__ void mma16816(float* c, const uint32_t* a, const uint32_t* b) {
    asm volatile(
        "mma.sync.aligned.m16n8k16.row.col.f32.f16.f16.f32 "
        "{%0,%1,%2,%3}, {%4,%5,%6,%7}, {%8,%9}, {%0,%1,%2,%3};"
        : "+f"(c[0]), "+f"(c[1]), "+f"(c[2]), "+f"(c[3])
        : "r"(a[0]), "r"(a[1]), "r"(a[2]), "r"(a[3]), "r"(b[0]), "r"(b[1]));
}

__device__ __forceinline__ unsigned int pack_h2(float a, float b) {
    __half2 p = __floats2half2_rn(a, b);
    return *reinterpret_cast<unsigned int*>(&p);
}

// ---------------- K-buildA: dense adjacency + degrees ----------
__global__ void k_buildA(const int* __restrict__ esrc, const int* __restrict__ edst) {
    int b = blockIdx.x, t = threadIdx.x;
    float* A = g_A + (size_t)b*65536;
    float4* A4 = (float4*)A;
    for (int i = t; i < 16384; i += 256) A4[i] = make_float4(0.f, 0.f, 0.f, 0.f);
    __shared__ int scnt[NPER];
    if (t < 256) scnt[t] = 0;
    __syncthreads();
    const int* s = esrc + b*EPER;
    const int* d = edst + b*EPER;
    for (int e = t; e < EPER; e += 256) {
        int dst = d[e], src = s[e];
        atomicAdd(&scnt[dst], 1);
        atomicAdd(&A[dst*256 + src], 1.0f);
    }
    __syncthreads();
    if (t < 256) {
        int c = scnt[t];
        g_ideg[b*NPER + t] = 1.0f / (float)(c > 0 ? c : 1);
    }
}

// ---------------- K-prepA: A -> exact fp16 A-frags ----------
__global__ void __launch_bounds__(256) k_prepA() {
    __shared__ float sm[16*256];
    int t = threadIdx.x;
    int b = blockIdx.x >> 4, mt = blockIdx.x & 15;
    const float4* src = (const float4*)(g_A + ((size_t)b*256 + mt*16)*256);
    #pragma unroll
    for (int k = 0; k < 4; k++) ((float4*)sm)[t + k*256] = src[t + k*256];
    __syncthreads();
    #pragma unroll
    for (int k = 0; k < 8; k++) {
        int w = t + k*256;
        int reg = w & 3, lane = (w >> 2) & 31, kc = w >> 7;
        int g = lane >> 2, tg = lane & 3;
        int row = g + (reg & 1)*8;
        int col = kc*16 + tg*2 + (reg >> 1)*8;
        g_Afrag[(size_t)(b*16 + mt)*2048 + w] = pack_h2(sm[row*256 + col], sm[row*256 + col + 1]);
    }
}

// ---------------- K-prep: X A-frags; W B-frags (single fp16) --------
__global__ void __launch_bounds__(256) k_prep(
        const float* __restrict__ h,
        const float* __restrict__ Wf, const float* __restrict__ Wp) {
    __shared__ float hs[16*256];
    int t = threadIdx.x;
    if (blockIdx.x < 1024) {
        int mt = blockIdx.x;
        const float4* src = (const float4*)(h + (size_t)mt*16*DIN);
        #pragma unroll
        for (int k = 0; k < 4; k++)
            ((float4*)hs)[t + k*256] = src[t + k*256];
        __syncthreads();
        #pragma unroll
        for (int k = 0; k < 8; k++) {
            int w = t + k*256;
            int reg = w & 3, lane = (w >> 2) & 31, kc = w >> 7;
            int g = lane >> 2, tg = lane & 3;
            int row = g + (reg & 1)*8;
            int wc = tg + (reg >> 1)*4;
            const float* hp = hs + row*256 + (kc*8 + wc)*2;
            g_Xf[(size_t)mt*2048 + w] = pack_h2(hp[0], hp[1]);
        }
    } else {
        int widx = (blockIdx.x - 1024)*256 + t;   // [0, 65536)
        int reg = widx & 1, lane = (widx >> 1) & 31, kc = (widx >> 6) & 15, nt = widx >> 10;
        int g = lane >> 2, tg = lane & 3;
        int n = nt*8 + g;
        int w = tg + reg*4;
        int k = (kc*8 + w)*2;
        int seg = n >> 7;
        const float* Wb = (seg < 2) ? Wf : Wp;
        int col = n & 127;
        int krow = k + ((seg & 1) ? 256 : 0);
        float x0 = Wb[(size_t)krow*128 + col];
        float x1 = Wb[(size_t)(krow+1)*128 + col];
        g_WTf[widx] = pack_h2(x0, x1);
    }
}

// ---------------- K-gemm: T = X @ Wcat (1-pass fp16) ----------------
// grid (128, 4); y in {0,2}: write fp32 T (top halves); y in {1,3}: emit Tf frags.
__global__ void __launch_bounds__(256) k_gemm_mma() {
    extern __shared__ float smT[];      // 128 x 128 staging (64KB) for frag emission
    int t = threadIdx.x, lane = t & 31, w = t >> 5;
    int wm = w & 1, wn = w >> 1;
    int mt0 = blockIdx.x*8 + wm*4;
    int nt0 = blockIdx.y*16 + wn*4;

    float acc[4][4][4];
    #pragma unroll
    for (int i = 0; i < 4; i++)
        #pragma unroll
        for (int j = 0; j < 4; j++)
            #pragma unroll
            for (int r = 0; r < 4; r++) acc[i][j][r] = 0.f;

    const uint4* X4 = (const uint4*)g_Xf;
    const uint2* W2 = (const uint2*)g_WTf;

    for (int kc = 0; kc < 16; kc++) {
        uint4 Af[4];
        uint2 Bf[4];
        #pragma unroll
        for (int i = 0; i < 4; i++)
            Af[i] = X4[((mt0 + i)*16 + kc)*32 + lane];
        #pragma unroll
        for (int j = 0; j < 4; j++)
            Bf[j] = W2[((nt0 + j)*16 + kc)*32 + lane];
        #pragma unroll
        for (int i = 0; i < 4; i++)
            #pragma unroll
            for (int j = 0; j < 4; j++)
                mma16816(acc[i][j], (const uint32_t*)&Af[i], (const uint32_t*)&Bf[j]);
    }

    int g = lane >> 2, tg = lane & 3;
    if ((blockIdx.y & 1) == 0) {
        #pragma unroll
        for (int i = 0; i < 4; i++) {
            #pragma unroll
            for (int j = 0; j < 4; j++) {
                size_t row = (size_t)(mt0 + i)*16 + g;
                size_t col = (size_t)(nt0 + j)*8 + tg*2;
                *(float2*)(g_T + row*512 + col)       = make_float2(acc[i][j][0], acc[i][j][1]);
                *(float2*)(g_T + (row + 8)*512 + col) = make_float2(acc[i][j][2], acc[i][j][3]);
            }
        }
    } else {
        #pragma unroll
        for (int i = 0; i < 4; i++) {
            #pragma unroll
            for (int j = 0; j < 4; j++) {
                int row = (wm*4 + i)*16 + g;
                int col = (wn*4 + j)*8 + tg*2;
                *(float2*)(smT + row*128 + col)       = make_float2(acc[i][j][0], acc[i][j][1]);
                *(float2*)(smT + (row + 8)*128 + col) = make_float2(acc[i][j][2], acc[i][j][3]);
            }
        }
        __syncthreads();
        int b = blockIdx.x >> 1, half = blockIdx.x & 1;
        int ntbase = (blockIdx.y == 1) ? 0 : 16;
        #pragma unroll
        for (int k = 0; k < 32; k++) {
            int w2 = t + k*256;               // [0, 8192)
            int reg = w2 & 1, ln = (w2 >> 1) & 31, ntl = (w2 >> 6) & 15, kcl = w2 >> 10;
            int gg = ln >> 2, tt = ln & 3;
            int n = ntl*8 + gg;
            int k0 = tt*2 + reg*8;
            int row = kcl*16 + k0;
            g_Tf[(size_t)b*32768 + (ntbase + ntl)*1024 + (half*8 + kcl)*64 + ln*2 + reg] =
                pack_h2(smT[row*128 + n], smT[(row + 1)*128 + n]);
        }
    }
}

// ---------------- K-agg2: AG = A @ [T_fbot|T_pbot] (1-pass) --------------------
__global__ void __launch_bounds__(256) k_agg2() {
    int t = threadIdx.x, lane = t & 31, w = t >> 5;
    int b = blockIdx.x, mh = blockIdx.y, nh = blockIdx.z;
    int wm = w & 1, wn = w >> 1;
    int mt0 = mh*8 + wm*4;
    int nt0 = nh*16 + wn*4;

    float acc[4][4][4];
    #pragma unroll
    for (int i = 0; i < 4; i++)
        #pragma unroll
        for (int j = 0; j < 4; j++)
            #pragma unroll
            for (int r = 0; r < 4; r++) acc[i][j][r] = 0.f;

    const uint4* A4 = (const uint4*)g_Afrag;
    const uint2* B2 = (const uint2*)g_Tf;

    for (int kc = 0; kc < 16; kc++) {
        uint4 Af[4];
        uint2 Bf[4];
        #pragma unroll
        for (int i = 0; i < 4; i++)
            Af[i] = A4[(size_t)(b*16 + mt0 + i)*512 + kc*32 + lane];
        #pragma unroll
        for (int j = 0; j < 4; j++)
            Bf[j] = B2[(size_t)b*16384 + (nt0 + j)*512 + kc*32 + lane];
        #pragma unroll
        for (int i = 0; i < 4; i++)
            #pragma unroll
            for (int j = 0; j < 4; j++)
                mma16816(acc[i][j], (const uint32_t*)&Af[i], (const uint32_t*)&Bf[j]);
    }

    int g = lane >> 2, tg = lane & 3;
    #pragma unroll
    for (int i = 0; i < 4; i++) {
        #pragma unroll
        for (int j = 0; j < 4; j++) {
            size_t row = (size_t)(mt0 + i)*16 + g;
            size_t col = (size_t)(nt0 + j)*8 + tg*2;
            *(float2*)(g_AG + ((size_t)b*256 + row)*256 + col)     = make_float2(acc[i][j][0], acc[i][j][1]);
            *(float2*)(g_AG + ((size_t)b*256 + row + 8)*256 + col) = make_float2(acc[i][j][2], acc[i][j][3]);
        }
    }
}

// ---------------- K-epi: z -> norm/relu(/softmax); emit S,F,S^T fragments ------
__global__ void __launch_bounds__(256) k_epi(const float* __restrict__ bf,
                                             const float* __restrict__ bp) {
    __shared__ float smF[16*128];
    __shared__ float smS[16*128];
    int b = blockIdx.x >> 4, kc = blockIdx.x & 15;
    int t = threadIdx.x, w = t >> 5, l = t & 31;

    #pragma unroll
    for (int i = 0; i < 4; i++) {
        int task = w*4 + i;
        int which = task >> 4, nl = task & 15;
        int gi = b*256 + kc*16 + nl;
        const float* bias = which ? bp : bf;
        float4 bias4 = *(const float4*)(bias + l*4);
        float4 top = *(const float4*)(g_T + (size_t)gi*512 + which*256 + l*4);
        float4 ag  = *(const float4*)(g_AG + (size_t)gi*256 + which*128 + l*4);
        float ideg = g_ideg[gi];

        float z0 = fmaf(ideg, ag.x, top.x) + bias4.x;
        float z1 = fmaf(ideg, ag.y, top.y) + bias4.y;
        float z2 = fmaf(ideg, ag.z, top.z) + bias4.z;
        float z3 = fmaf(ideg, ag.w, top.w) + bias4.w;

        float ss = z0*z0 + z1*z1 + z2*z2 + z3*z3;
        #pragma unroll
        for (int o = 16; o > 0; o >>= 1) ss += __shfl_xor_sync(0xffffffffu, ss, o);
        float inv = rsqrtf(fmaxf(ss, 1e-24f));
        z0 = fmaxf(z0*inv, 0.f); z1 = fmaxf(z1*inv, 0.f);
        z2 = fmaxf(z2*inv, 0.f); z3 = fmaxf(z3*inv, 0.f);

        if (which == 0) {
            smF[nl*128 + l*4 + 0] = z0;
            smF[nl*128 + l*4 + 1] = z1;
            smF[nl*128 + l*4 + 2] = z2;
            smF[nl*128 + l*4 + 3] = z3;
        } else {
            float m = fmaxf(fmaxf(z0, z1), fmaxf(z2, z3));
            #pragma unroll
            for (int o = 16; o > 0; o >>= 1) m = fmaxf(m, __shfl_xor_sync(0xffffffffu, m, o));
            float e0 = __expf(z0 - m), e1 = __expf(z1 - m);
            float e2 = __expf(z2 - m), e3 = __expf(z3 - m);
            float s = (e0 + e1) + (e2 + e3);
            #pragma unroll
            for (int o = 16; o > 0; o >>= 1) s += __shfl_xor_sync(0xffffffffu, s, o);
            float isum = 1.0f / s;
            smS[nl*128 + l*4 + 0] = e0*isum;
            smS[nl*128 + l*4 + 1] = e1*isum;
            smS[nl*128 + l*4 + 2] = e2*isum;
            smS[nl*128 + l*4 + 3] = e3*isum;
        }
    }
    __syncthreads();

    #pragma unroll
    for (int k = 0; k < 4; k++) {
        int w2 = t + k*256;
        int reg = w2 & 1, lane = (w2 >> 1) & 31, nt = w2 >> 6;
        int g = lane >> 2, tg = lane & 3;
        int n = nt*8 + g;
        int k0 = tg*2 + reg*8;
        size_t idx = (size_t)b*16384 + nt*1024 + kc*64 + (w2 & 63);
        g_Sf[idx] = pack_h2(smS[k0*128 + n], smS[(k0+1)*128 + n]);
        g_Ff[idx] = pack_h2(smF[k0*128 + n], smF[(k0+1)*128 + n]);
    }
    #pragma unroll
    for (int k = 0; k < 4; k++) {
        int w2 = t + k*256;
        int reg = w2 & 3, lane = (w2 >> 2) & 31, mt = w2 >> 7;
        int g = lane >> 2, tg = lane & 3;
        int m = mt*16 + g + (reg & 1)*8;
        int k0 = tg*2 + (reg >> 1)*8;
        g_STf[(size_t)b*16384 + mt*2048 + kc*128 + lane*4 + reg] =
            pack_h2(smS[k0*128 + m], smS[(k0+1)*128 + m]);
    }
}

// ---------------- K-as2: AS = A @ S -> emit ASf frags directly --------
__global__ void __launch_bounds__(256) k_as2() {
    extern __shared__ float smT[];      // 128 x 128
    int t = threadIdx.x, lane = t & 31, w = t >> 5;
    int b = blockIdx.x, mh = blockIdx.y;
    int wm = w & 1, wn = w >> 1;
    int mt0 = mh*8 + wm*4;
    int nt0 = wn*4;

    float acc[4][4][4];
    #pragma unroll
    for (int i = 0; i < 4; i++)
        #pragma unroll
        for (int j = 0; j < 4; j++)
            #pragma unroll
            for (int r = 0; r < 4; r++) acc[i][j][r] = 0.f;

    const uint4* A4 = (const uint4*)g_Afrag;
    const uint2* B2 = (const uint2*)g_Sf;

    for (int kc = 0; kc < 16; kc++) {
        uint4 Af[4];
        uint2 Bf[4];
        #pragma unroll
        for (int i = 0; i < 4; i++)
            Af[i] = A4[(size_t)(b*16 + mt0 + i)*512 + kc*32 + lane];
        #pragma unroll
        for (int j = 0; j < 4; j++)
            Bf[j] = B2[(size_t)b*8192 + (nt0 + j)*512 + kc*32 + lane];
        #pragma unroll
        for (int i = 0; i < 4; i++)
            #pragma unroll
            for (int j = 0; j < 4; j++)
                mma16816(acc[i][j], (const uint32_t*)&Af[i], (const uint32_t*)&Bf[j]);
    }

    int g = lane >> 2, tg = lane & 3;
    #pragma unroll
    for (int i = 0; i < 4; i++) {
        #pragma unroll
        for (int j = 0; j < 4; j++) {
            int row = (wm*4 + i)*16 + g;
            int col = (wn*4 + j)*8 + tg*2;
            *(float2*)(smT + row*128 + col)       = make_float2(acc[i][j][0], acc[i][j][1]);
            *(float2*)(smT + (row + 8)*128 + col) = make_float2(acc[i][j][2], acc[i][j][3]);
        }
    }
    __syncthreads();
    #pragma unroll
    for (int k = 0; k < 32; k++) {
        int w2 = t + k*256;               // [0, 8192)
        int reg = w2 & 1, ln = (w2 >> 1) & 31, ntl = (w2 >> 6) & 15, kcl = w2 >> 10;
        int gg = ln >> 2, tt = ln & 3;
        int n = ntl*8 + gg;
        int k0 = tt*2 + reg*8;
        int row = kcl*16 + k0;
        g_ASf[(size_t)b*16384 + ntl*1024 + (mh*8 + kcl)*64 + ln*2 + reg] =
            pack_h2(smT[row*128 + n], smT[(row + 1)*128 + n]);
    }
}

// ---------------- K-pool: D = S^T @ (F or AS) via HMMA ----------
__global__ void __launch_bounds__(256) k_pool_mma(float* __restrict__ out, int which) {
    int t = threadIdx.x, lane = t & 31, w = t >> 5;
    int b = blockIdx.x;
    int wm = w & 1, wn = w >> 1;
    int mt0 = wm*4;
    int nt0 = wn*4;

    float acc[4][4][4];
    #pragma unroll
    for (int i = 0; i < 4; i++)
        #pragma unroll
        for (int j = 0; j < 4; j++)
            #pragma unroll
            for (int r = 0; r < 4; r++) acc[i][j][r] = 0.f;

    const uint4* A4 = (const uint4*)g_STf;
    const uint2* B2 = (const uint2*)(which ? g_ASf : g_Ff);

    for (int kc = 0; kc < 16; kc++) {
        uint4 Af[4];
        uint2 Bf[4];
        #pragma unroll
        for (int i = 0; i < 4; i++)
            Af[i] = A4[(size_t)b*4096 + (mt0 + i)*512 + kc*32 + lane];
        #pragma unroll
        for (int j = 0; j < 4; j++)
            Bf[j] = B2[(size_t)b*8192 + (nt0 + j)*512 + kc*32 + lane];
        #pragma unroll
        for (int i = 0; i < 4; i++)
            #pragma unroll
            for (int j = 0; j < 4; j++)
                mma16816(acc[i][j], (const uint32_t*)&Af[i], (const uint32_t*)&Bf[j]);
    }

    int g = lane >> 2, tg = lane & 3;
    #pragma unroll
    for (int i = 0; i < 4; i++) {
        #pragma unroll
        for (int j = 0; j < 4; j++) {
            size_t row = (size_t)(mt0 + i)*16 + g;
            size_t col = (size_t)(nt0 + j)*8 + tg*2;
            size_t grow = (size_t)b*128 + row;
            size_t base = which ? (grow*ADJ_N + (size_t)b*128 + col)
                                : ((size_t)ADJ_ELEMS + grow*DOUT + col);
            *(float2*)(out + base) = make_float2(acc[i][j][0], acc[i][j][1]);
            size_t grow2 = grow + 8;
            size_t base2 = which ? (grow2*ADJ_N + (size_t)b*128 + col)
                                 : ((size_t)ADJ_ELEMS + grow2*DOUT + col);
            *(float2*)(out + base2) = make_float2(acc[i][j][2], acc[i][j][3]);
        }
    }
}

// ---------------- launch ----------------
extern "C" void kernel_launch(void* const* d_in, const int* in_sizes, int n_in,
                              void* d_out, int out_size) {
    const float* h    = (const float*)d_in[0];
    const int*   esrc = (const int*)d_in[1];
    const int*   edst = (const int*)d_in[2];
    const float* Wf   = (const float*)d_in[3];
    const float* bf   = (const float*)d_in[4];
    const float* Wp   = (const float*)d_in[5];
    const float* bp   = (const float*)d_in[6];
    float* out = (float*)d_out;

    static cudaStream_t s_side = nullptr;
    static cudaEvent_t  e_fork = nullptr, e_build = nullptr, e_join = nullptr;
    static bool attr_done = false;
    if (!s_side) {
        cudaStreamCreateWithFlags(&s_side, cudaStreamNonBlocking);
        cudaEventCreateWithFlags(&e_fork,  cudaEventDisableTiming);
        cudaEventCreateWithFlags(&e_build, cudaEventDisableTiming);
        cudaEventCreateWithFlags(&e_join,  cudaEventDisableTiming);
    }
    if (!attr_done) {
        cudaFuncSetAttribute(k_gemm_mma, cudaFuncAttributeMaxDynamicSharedMemorySize, 65536);
        cudaFuncSetAttribute(k_as2,      cudaFuncAttributeMaxDynamicSharedMemorySize, 65536);
        attr_done = true;
    }

    // side stream: buildA -> prepA -> (e_build) -> adj memset -> (e_join)
    cudaEventRecord(e_fork, 0);
    cudaStreamWaitEvent(s_side, e_fork, 0);
    k_buildA<<<NB, 256, 0, s_side>>>(esrc, edst);
    k_prepA<<<1024, 256, 0, s_side>>>();
    cudaEventRecord(e_build, s_side);
    cudaMemsetAsync(d_out, 0, (size_t)ADJ_ELEMS * sizeof(float), s_side);
    cudaEventRecord(e_join, s_side);

    // main stream
    k_prep<<<1280, 256>>>(h, Wf, Wp);
    k_gemm_mma<<<dim3(128, 4), 256, 65536>>>();
    cudaStreamWaitEvent(0, e_build, 0);
    k_agg2<<<dim3(NB, 2, 2), 256>>>();
    k_epi<<<1024, 256>>>(bf, bp);
    k_pool_mma<<<NB, 256>>>(out, 0);     // h_pool region: no memset dependency
    k_as2<<<dim3(NB, 2), 256, 65536>>>();
    cudaStreamWaitEvent(0, e_join, 0);
    k_pool_mma<<<NB, 256>>>(out, 1);     // adj diagonal blocks: after memset
}

// round 17
// speedup vs baseline: 1.4581x; 1.1636x over previous
#include <cuda_runtime.h>
#include <cuda_fp16.h>
#include <math.h>
#include <stdint.h>

#define NB   64
#define NPER 256
#define DIN  256
#define DOUT 128
#define EPER 8192
#define ADJ_N 8192
#define ADJ_ELEMS (67108864u)
#define NROWS (NB*NPER)          // 16384

// ---------------- scratch ----------------
__device__ float g_T[NROWS*512];          // only cols 0..127 (f_top) and 256..383 (p_top) used
__device__ float g_A[NB*NPER*NPER];       // dense adjacency counts (fp32)
__device__ float g_AG[NB*NPER*256];       // A @ [T_fbot|T_pbot]
__device__ float g_ideg[NROWS];
// fp16x2 fragment arrays (uint32 words)
__device__ unsigned int g_Xf[NROWS*128];      // X      A-frag [mt][kc][lane][4]
__device__ unsigned int g_WTf[64*1024];       // Wcat^T B-frag [nt64][kc][lane][2]
__device__ unsigned int g_Afrag[NB*16*2048];  // A (exact) A-frag [b][mt][kc][lane][4]
__device__ unsigned int g_Tf[NB*32768];       // T_bot  B-frag [b][nt32][kc][lane][2]
__device__ unsigned int g_Sf[NB*16384];       // assign B-frag [b][nt16][kc][lane][2]
__device__ unsigned int g_Ff[NB*16384];       // feat   B-frag
__device__ unsigned int g_ASf[NB*16384];      // AS     B-frag
__device__ unsigned int g_STf[NB*16384];      // S^T    A-frag [b][mt8][kc][lane][4]

// ---------------- mma.sync fp16 ----------
__device__ __forceinline__ void mma16816(float* c, const uint32_t* a, const uint32_t* b) {
    asm volatile(
        "mma.sync.aligned.m16n8k16.row.col.f32.f16.f16.f32 "
        "{%0,%1,%2,%3}, {%4,%5,%6,%7}, {%8,%9}, {%0,%1,%2,%3};"
        : "+f"(c[0]), "+f"(c[1]), "+f"(c[2]), "+f"(c[3])
        : "r"(a[0]), "r"(a[1]), "r"(a[2]), "r"(a[3]), "r"(b[0]), "r"(b[1]));
}

__device__ __forceinline__ unsigned int pack_h2(float a, float b) {
    __half2 p = __floats2half2_rn(a, b);
    return *reinterpret_cast<unsigned int*>(&p);
}

// ---------------- K-zero: zero adj region EXCEPT diagonal 128x128 blocks ------
// adj row r belongs to graph b = r>>7; skip float4 cols [b*32, b*32+32).
__global__ void __launch_bounds__(256) k_zero(float4* __restrict__ out4) {
    unsigned int stride = gridDim.x * 256;
    float4 z = make_float4(0.f, 0.f, 0.f, 0.f);
    for (unsigned int i = blockIdx.x*256 + threadIdx.x; i < 16777216u; i += stride) {
        unsigned int c4 = i & 2047u;
        unsigned int r  = i >> 11;
        if ((c4 >> 5) != (r >> 7)) out4[i] = z;
    }
}

// ---------------- K-buildA: dense adjacency + degrees ----------
__global__ void k_buildA(const int* __restrict__ esrc, const int* __restrict__ edst) {
    int b = blockIdx.x, t = threadIdx.x;
    float* A = g_A + (size_t)b*65536;
    float4* A4 = (float4*)A;
    for (int i = t; i < 16384; i += 256) A4[i] = make_float4(0.f, 0.f, 0.f, 0.f);
    __shared__ int scnt[NPER];
    if (t < 256) scnt[t] = 0;
    __syncthreads();
    const int* s = esrc + b*EPER;
    const int* d = edst + b*EPER;
    for (int e = t; e < EPER; e += 256) {
        int dst = d[e], src = s[e];
        atomicAdd(&scnt[dst], 1);
        atomicAdd(&A[dst*256 + src], 1.0f);
    }
    __syncthreads();
    if (t < 256) {
        int c = scnt[t];
        g_ideg[b*NPER + t] = 1.0f / (float)(c > 0 ? c : 1);
    }
}

// ---------------- K-prepA: A -> exact fp16 A-frags ----------
__global__ void __launch_bounds__(256) k_prepA() {
    __shared__ float sm[16*256];
    int t = threadIdx.x;
    int b = blockIdx.x >> 4, mt = blockIdx.x & 15;
    const float4* src = (const float4*)(g_A + ((size_t)b*256 + mt*16)*256);
    #pragma unroll
    for (int k = 0; k < 4; k++) ((float4*)sm)[t + k*256] = src[t + k*256];
    __syncthreads();
    #pragma unroll
    for (int k = 0; k < 8; k++) {
        int w = t + k*256;
        int reg = w & 3, lane = (w >> 2) & 31, kc = w >> 7;
        int g = lane >> 2, tg = lane & 3;
        int row = g + (reg & 1)*8;
        int col = kc*16 + tg*2 + (reg >> 1)*8;
        g_Afrag[(size_t)(b*16 + mt)*2048 + w] = pack_h2(sm[row*256 + col], sm[row*256 + col + 1]);
    }
}

// ---------------- K-prep: X A-frags; W B-frags (single fp16) --------
__global__ void __launch_bounds__(256) k_prep(
        const float* __restrict__ h,
        const float* __restrict__ Wf, const float* __restrict__ Wp) {
    __shared__ float hs[16*256];
    int t = threadIdx.x;
    if (blockIdx.x < 1024) {
        int mt = blockIdx.x;
        const float4* src = (const float4*)(h + (size_t)mt*16*DIN);
        #pragma unroll
        for (int k = 0; k < 4; k++)
            ((float4*)hs)[t + k*256] = src[t + k*256];
        __syncthreads();
        #pragma unroll
        for (int k = 0; k < 8; k++) {
            int w = t + k*256;
            int reg = w & 3, lane = (w >> 2) & 31, kc = w >> 7;
            int g = lane >> 2, tg = lane & 3;
            int row = g + (reg & 1)*8;
            int wc = tg + (reg >> 1)*4;
            const float* hp = hs + row*256 + (kc*8 + wc)*2;
            g_Xf[(size_t)mt*2048 + w] = pack_h2(hp[0], hp[1]);
        }
    } else {
        int widx = (blockIdx.x - 1024)*256 + t;   // [0, 65536)
        int reg = widx & 1, lane = (widx >> 1) & 31, kc = (widx >> 6) & 15, nt = widx >> 10;
        int g = lane >> 2, tg = lane & 3;
        int n = nt*8 + g;
        int w = tg + reg*4;
        int k = (kc*8 + w)*2;
        int seg = n >> 7;
        const float* Wb = (seg < 2) ? Wf : Wp;
        int col = n & 127;
        int krow = k + ((seg & 1) ? 256 : 0);
        float x0 = Wb[(size_t)krow*128 + col];
        float x1 = Wb[(size_t)(krow+1)*128 + col];
        g_WTf[widx] = pack_h2(x0, x1);
    }
}

// ---------------- K-gemm: T = X @ Wcat (1-pass fp16) ----------------
// grid (128, 4); y in {0,2}: write fp32 T (top halves); y in {1,3}: emit Tf frags.
__global__ void __launch_bounds__(256) k_gemm_mma() {
    extern __shared__ float smT[];      // 128 x 128 staging (64KB) for frag emission
    int t = threadIdx.x, lane = t & 31, w = t >> 5;
    int wm = w & 1, wn = w >> 1;
    int mt0 = blockIdx.x*8 + wm*4;
    int nt0 = blockIdx.y*16 + wn*4;

    float acc[4][4][4];
    #pragma unroll
    for (int i = 0; i < 4; i++)
        #pragma unroll
        for (int j = 0; j < 4; j++)
            #pragma unroll
            for (int r = 0; r < 4; r++) acc[i][j][r] = 0.f;

    const uint4* X4 = (const uint4*)g_Xf;
    const uint2* W2 = (const uint2*)g_WTf;

    for (int kc = 0; kc < 16; kc++) {
        uint4 Af[4];
        uint2 Bf[4];
        #pragma unroll
        for (int i = 0; i < 4; i++)
            Af[i] = X4[((mt0 + i)*16 + kc)*32 + lane];
        #pragma unroll
        for (int j = 0; j < 4; j++)
            Bf[j] = W2[((nt0 + j)*16 + kc)*32 + lane];
        #pragma unroll
        for (int i = 0; i < 4; i++)
            #pragma unroll
            for (int j = 0; j < 4; j++)
                mma16816(acc[i][j], (const uint32_t*)&Af[i], (const uint32_t*)&Bf[j]);
    }

    int g = lane >> 2, tg = lane & 3;
    if ((blockIdx.y & 1) == 0) {
        #pragma unroll
        for (int i = 0; i < 4; i++) {
            #pragma unroll
            for (int j = 0; j < 4; j++) {
                size_t row = (size_t)(mt0 + i)*16 + g;
                size_t col = (size_t)(nt0 + j)*8 + tg*2;
                *(float2*)(g_T + row*512 + col)       = make_float2(acc[i][j][0], acc[i][j][1]);
                *(float2*)(g_T + (row + 8)*512 + col) = make_float2(acc[i][j][2], acc[i][j][3]);
            }
        }
    } else {
        #pragma unroll
        for (int i = 0; i < 4; i++) {
            #pragma unroll
            for (int j = 0; j < 4; j++) {
                int row = (wm*4 + i)*16 + g;
                int col = (wn*4 + j)*8 + tg*2;
                *(float2*)(smT + row*128 + col)       = make_float2(acc[i][j][0], acc[i][j][1]);
                *(float2*)(smT + (row + 8)*128 + col) = make_float2(acc[i][j][2], acc[i][j][3]);
            }
        }
        __syncthreads();
        int b = blockIdx.x >> 1, half = blockIdx.x & 1;
        int ntbase = (blockIdx.y == 1) ? 0 : 16;
        #pragma unroll
        for (int k = 0; k < 32; k++) {
            int w2 = t + k*256;               // [0, 8192)
            int reg = w2 & 1, ln = (w2 >> 1) & 31, ntl = (w2 >> 6) & 15, kcl = w2 >> 10;
            int gg = ln >> 2, tt = ln & 3;
            int n = ntl*8 + gg;
            int k0 = tt*2 + reg*8;
            int row = kcl*16 + k0;
            g_Tf[(size_t)b*32768 + (ntbase + ntl)*1024 + (half*8 + kcl)*64 + ln*2 + reg] =
                pack_h2(smT[row*128 + n], smT[(row + 1)*128 + n]);
        }
    }
}

// ---------------- K-agg2: AG = A @ [T_fbot|T_pbot] (1-pass) --------------------
__global__ void __launch_bounds__(256) k_agg2() {
    int t = threadIdx.x, lane = t & 31, w = t >> 5;
    int b = blockIdx.x, mh = blockIdx.y, nh = blockIdx.z;
    int wm = w & 1, wn = w >> 1;
    int mt0 = mh*8 + wm*4;
    int nt0 = nh*16 + wn*4;

    float acc[4][4][4];
    #pragma unroll
    for (int i = 0; i < 4; i++)
        #pragma unroll
        for (int j = 0; j < 4; j++)
            #pragma unroll
            for (int r = 0; r < 4; r++) acc[i][j][r] = 0.f;

    const uint4* A4 = (const uint4*)g_Afrag;
    const uint2* B2 = (const uint2*)g_Tf;

    for (int kc = 0; kc < 16; kc++) {
        uint4 Af[4];
        uint2 Bf[4];
        #pragma unroll
        for (int i = 0; i < 4; i++)
            Af[i] = A4[(size_t)(b*16 + mt0 + i)*512 + kc*32 + lane];
        #pragma unroll
        for (int j = 0; j < 4; j++)
            Bf[j] = B2[(size_t)b*16384 + (nt0 + j)*512 + kc*32 + lane];
        #pragma unroll
        for (int i = 0; i < 4; i++)
            #pragma unroll
            for (int j = 0; j < 4; j++)
                mma16816(acc[i][j], (const uint32_t*)&Af[i], (const uint32_t*)&Bf[j]);
    }

    int g = lane >> 2, tg = lane & 3;
    #pragma unroll
    for (int i = 0; i < 4; i++) {
        #pragma unroll
        for (int j = 0; j < 4; j++) {
            size_t row = (size_t)(mt0 + i)*16 + g;
            size_t col = (size_t)(nt0 + j)*8 + tg*2;
            *(float2*)(g_AG + ((size_t)b*256 + row)*256 + col)     = make_float2(acc[i][j][0], acc[i][j][1]);
            *(float2*)(g_AG + ((size_t)b*256 + row + 8)*256 + col) = make_float2(acc[i][j][2], acc[i][j][3]);
        }
    }
}

// ---------------- K-epi: z -> norm/relu(/softmax); emit S,F,S^T fragments ------
__global__ void __launch_bounds__(256) k_epi(const float* __restrict__ bf,
                                             const float* __restrict__ bp) {
    __shared__ float smF[16*128];
    __shared__ float smS[16*128];
    int b = blockIdx.x >> 4, kc = blockIdx.x & 15;
    int t = threadIdx.x, w = t >> 5, l = t & 31;

    #pragma unroll
    for (int i = 0; i < 4; i++) {
        int task = w*4 + i;
        int which = task >> 4, nl = task & 15;
        int gi = b*256 + kc*16 + nl;
        const float* bias = which ? bp : bf;
        float4 bias4 = *(const float4*)(bias + l*4);
        float4 top = *(const float4*)(g_T + (size_t)gi*512 + which*256 + l*4);
        float4 ag  = *(const float4*)(g_AG + (size_t)gi*256 + which*128 + l*4);
        float ideg = g_ideg[gi];

        float z0 = fmaf(ideg, ag.x, top.x) + bias4.x;
        float z1 = fmaf(ideg, ag.y, top.y) + bias4.y;
        float z2 = fmaf(ideg, ag.z, top.z) + bias4.z;
        float z3 = fmaf(ideg, ag.w, top.w) + bias4.w;

        float ss = z0*z0 + z1*z1 + z2*z2 + z3*z3;
        #pragma unroll
        for (int o = 16; o > 0; o >>= 1) ss += __shfl_xor_sync(0xffffffffu, ss, o);
        float inv = rsqrtf(fmaxf(ss, 1e-24f));
        z0 = fmaxf(z0*inv, 0.f); z1 = fmaxf(z1*inv, 0.f);
        z2 = fmaxf(z2*inv, 0.f); z3 = fmaxf(z3*inv, 0.f);

        if (which == 0) {
            smF[nl*128 + l*4 + 0] = z0;
            smF[nl*128 + l*4 + 1] = z1;
            smF[nl*128 + l*4 + 2] = z2;
            smF[nl*128 + l*4 + 3] = z3;
        } else {
            float m = fmaxf(fmaxf(z0, z1), fmaxf(z2, z3));
            #pragma unroll
            for (int o = 16; o > 0; o >>= 1) m = fmaxf(m, __shfl_xor_sync(0xffffffffu, m, o));
            float e0 = __expf(z0 - m), e1 = __expf(z1 - m);
            float e2 = __expf(z2 - m), e3 = __expf(z3 - m);
            float s = (e0 + e1) + (e2 + e3);
            #pragma unroll
            for (int o = 16; o > 0; o >>= 1) s += __shfl_xor_sync(0xffffffffu, s, o);
            float isum = 1.0f / s;
            smS[nl*128 + l*4 + 0] = e0*isum;
            smS[nl*128 + l*4 + 1] = e1*isum;
            smS[nl*128 + l*4 + 2] = e2*isum;
            smS[nl*128 + l*4 + 3] = e3*isum;
        }
    }
    __syncthreads();

    #pragma unroll
    for (int k = 0; k < 4; k++) {
        int w2 = t + k*256;
        int reg = w2 & 1, lane = (w2 >> 1) & 31, nt = w2 >> 6;
        int g = lane >> 2, tg = lane & 3;
        int n = nt*8 + g;
        int k0 = tg*2 + reg*8;
        size_t idx = (size_t)b*16384 + nt*1024 + kc*64 + (w2 & 63);
        g_Sf[idx] = pack_h2(smS[k0*128 + n], smS[(k0+1)*128 + n]);
        g_Ff[idx] = pack_h2(smF[k0*128 + n], smF[(k0+1)*128 + n]);
    }
    #pragma unroll
    for (int k = 0; k < 4; k++) {
        int w2 = t + k*256;
        int reg = w2 & 3, lane = (w2 >> 2) & 31, mt = w2 >> 7;
        int g = lane >> 2, tg = lane & 3;
        int m = mt*16 + g + (reg & 1)*8;
        int k0 = tg*2 + (reg >> 1)*8;
        g_STf[(size_t)b*16384 + mt*2048 + kc*128 + lane*4 + reg] =
            pack_h2(smS[k0*128 + m], smS[(k0+1)*128 + m]);
    }
}

// ---------------- K-as2: AS = A @ S -> emit ASf frags directly --------
__global__ void __launch_bounds__(256) k_as2() {
    extern __shared__ float smT[];      // 128 x 128
    int t = threadIdx.x, lane = t & 31, w = t >> 5;
    int b = blockIdx.x, mh = blockIdx.y;
    int wm = w & 1, wn = w >> 1;
    int mt0 = mh*8 + wm*4;
    int nt0 = wn*4;

    float acc[4][4][4];
    #pragma unroll
    for (int i = 0; i < 4; i++)
        #pragma unroll
        for (int j = 0; j < 4; j++)
            #pragma unroll
            for (int r = 0; r < 4; r++) acc[i][j][r] = 0.f;

    const uint4* A4 = (const uint4*)g_Afrag;
    const uint2* B2 = (const uint2*)g_Sf;

    for (int kc = 0; kc < 16; kc++) {
        uint4 Af[4];
        uint2 Bf[4];
        #pragma unroll
        for (int i = 0; i < 4; i++)
            Af[i] = A4[(size_t)(b*16 + mt0 + i)*512 + kc*32 + lane];
        #pragma unroll
        for (int j = 0; j < 4; j++)
            Bf[j] = B2[(size_t)b*8192 + (nt0 + j)*512 + kc*32 + lane];
        #pragma unroll
        for (int i = 0; i < 4; i++)
            #pragma unroll
            for (int j = 0; j < 4; j++)
                mma16816(acc[i][j], (const uint32_t*)&Af[i], (const uint32_t*)&Bf[j]);
    }

    int g = lane >> 2, tg = lane & 3;
    #pragma unroll
    for (int i = 0; i < 4; i++) {
        #pragma unroll
        for (int j = 0; j < 4; j++) {
            int row = (wm*4 + i)*16 + g;
            int col = (wn*4 + j)*8 + tg*2;
            *(float2*)(smT + row*128 + col)       = make_float2(acc[i][j][0], acc[i][j][1]);
            *(float2*)(smT + (row + 8)*128 + col) = make_float2(acc[i][j][2], acc[i][j][3]);
        }
    }
    __syncthreads();
    #pragma unroll
    for (int k = 0; k < 32; k++) {
        int w2 = t + k*256;               // [0, 8192)
        int reg = w2 & 1, ln = (w2 >> 1) & 31, ntl = (w2 >> 6) & 15, kcl = w2 >> 10;
        int gg = ln >> 2, tt = ln & 3;
        int n = ntl*8 + gg;
        int k0 = tt*2 + reg*8;
        int row = kcl*16 + k0;
        g_ASf[(size_t)b*16384 + ntl*1024 + (mh*8 + kcl)*64 + ln*2 + reg] =
            pack_h2(smT[row*128 + n], smT[(row + 1)*128 + n]);
    }
}

// ---------------- K-pool: D = S^T @ (F or AS) via HMMA; which = blockIdx.y -----
__global__ void __launch_bounds__(256) k_pool_mma(float* __restrict__ out) {
    int t = threadIdx.x, lane = t & 31, w = t >> 5;
    int b = blockIdx.x, which = blockIdx.y;
    int wm = w & 1, wn = w >> 1;
    int mt0 = wm*4;
    int nt0 = wn*4;

    float acc[4][4][4];
    #pragma unroll
    for (int i = 0; i < 4; i++)
        #pragma unroll
        for (int j = 0; j < 4; j++)
            #pragma unroll
            for (int r = 0; r < 4; r++) acc[i][j][r] = 0.f;

    const uint4* A4 = (const uint4*)g_STf;
    const uint2* B2 = (const uint2*)(which ? g_ASf : g_Ff);

    for (int kc = 0; kc < 16; kc++) {
        uint4 Af[4];
        uint2 Bf[4];
        #pragma unroll
        for (int i = 0; i < 4; i++)
            Af[i] = A4[(size_t)b*4096 + (mt0 + i)*512 + kc*32 + lane];
        #pragma unroll
        for (int j = 0; j < 4; j++)
            Bf[j] = B2[(size_t)b*8192 + (nt0 + j)*512 + kc*32 + lane];
        #pragma unroll
        for (int i = 0; i < 4; i++)
            #pragma unroll
            for (int j = 0; j < 4; j++)
                mma16816(acc[i][j], (const uint32_t*)&Af[i], (const uint32_t*)&Bf[j]);
    }

    int g = lane >> 2, tg = lane & 3;
    #pragma unroll
    for (int i = 0; i < 4; i++) {
        #pragma unroll
        for (int j = 0; j < 4; j++) {
            size_t row = (size_t)(mt0 + i)*16 + g;
            size_t col = (size_t)(nt0 + j)*8 + tg*2;
            size_t grow = (size_t)b*128 + row;
            size_t base = which ? (grow*ADJ_N + (size_t)b*128 + col)
                                : ((size_t)ADJ_ELEMS + grow*DOUT + col);
            *(float2*)(out + base) = make_float2(acc[i][j][0], acc[i][j][1]);
            size_t grow2 = grow + 8;
            size_t base2 = which ? (grow2*ADJ_N + (size_t)b*128 + col)
                                 : ((size_t)ADJ_ELEMS + grow2*DOUT + col);
            *(float2*)(out + base2) = make_float2(acc[i][j][2], acc[i][j][3]);
        }
    }
}

// ---------------- launch ----------------
extern "C" void kernel_launch(void* const* d_in, const int* in_sizes, int n_in,
                              void* d_out, int out_size) {
    const float* h    = (const float*)d_in[0];
    const int*   esrc = (const int*)d_in[1];
    const int*   edst = (const int*)d_in[2];
    const float* Wf   = (const float*)d_in[3];
    const float* bf   = (const float*)d_in[4];
    const float* Wp   = (const float*)d_in[5];
    const float* bp   = (const float*)d_in[6];
    float* out = (float*)d_out;

    static cudaStream_t s_side = nullptr;
    static cudaEvent_t  e_fork = nullptr, e_build = nullptr, e_done = nullptr;
    static bool attr_done = false;
    if (!s_side) {
        cudaStreamCreateWithFlags(&s_side, cudaStreamNonBlocking);
        cudaEventCreateWithFlags(&e_fork,  cudaEventDisableTiming);
        cudaEventCreateWithFlags(&e_build, cudaEventDisableTiming);
        cudaEventCreateWithFlags(&e_done,  cudaEventDisableTiming);
    }
    if (!attr_done) {
        cudaFuncSetAttribute(k_gemm_mma, cudaFuncAttributeMaxDynamicSharedMemorySize, 65536);
        cudaFuncSetAttribute(k_as2,      cudaFuncAttributeMaxDynamicSharedMemorySize, 65536);
        attr_done = true;
    }

    // side stream: buildA -> (e_build) -> zero adj (off-diagonal only) -> (e_done)
    cudaEventRecord(e_fork, 0);
    cudaStreamWaitEvent(s_side, e_fork, 0);
    k_buildA<<<NB, 256, 0, s_side>>>(esrc, edst);
    cudaEventRecord(e_build, s_side);
    k_zero<<<4096, 256, 0, s_side>>>((float4*)out);
    cudaEventRecord(e_done, s_side);

    // main stream — pool has NO dependency on the zeroing (disjoint addresses)
    k_prep<<<1280, 256>>>(h, Wf, Wp);
    k_gemm_mma<<<dim3(128, 4), 256, 65536>>>();
    cudaStreamWaitEvent(0, e_build, 0);
    k_prepA<<<1024, 256>>>();
    k_agg2<<<dim3(NB, 2, 2), 256>>>();
    k_epi<<<1024, 256>>>(bf, bp);
    k_as2<<<dim3(NB, 2), 256, 65536>>>();
    k_pool_mma<<<dim3(NB, 2), 256>>>(out);
    cudaStreamWaitEvent(0, e_done, 0);   // capture join only
}